// round 14
// baseline (speedup 1.0000x reference)
#include <cuda_runtime.h>
#include <cstdint>

// KANLayer: out[b,o] = sum_i [ bias_w[o,i]*leaky(x[b,i]) + layer_w[o,i]*edge_mlp_{o,i}(x[b,i]) ]
// B=1024, I=64, O=64, H=32.
// R11 = resubmit of R10 (container infra failure, kernel never ran):
// R9 (f32x2 packed along h) + fixed A->B race via W2 LDG hoist + deferred STS.

#define FMA2(d, a, b, c) \
    asm("fma.rn.f32x2 %0, %1, %2, %3;" : "=l"(d) : "l"(a), "l"(b), "l"(c))

constexpr int Bsz = 1024, Isz = 64, Osz = 64, Hsz = 32;
constexpr int BT = 128;
constexpr int THREADS = 128;
constexpr int ZSPLIT = 4;
constexpr int IPB = Isz / ZSPLIT;          // 16

constexpr int H1S = 36;                    // h1 row stride (floats) = 144B
constexpr int W2S = 36;                    // w2 row stride (floats) = 144B

__device__ float g_scratch[ZSPLIT * Bsz * Osz];

__device__ __forceinline__ float leaky(float v) { return fmaxf(v, 0.01f * v); }

__global__ __launch_bounds__(THREADS) void kan_kernel(
    const float* __restrict__ x,  const float* __restrict__ W1,
    const float* __restrict__ b1, const float* __restrict__ W2,
    const float* __restrict__ b2, const float* __restrict__ W3,
    const float* __restrict__ b3, const float* __restrict__ lw,
    const float* __restrict__ bw)
{
    __shared__ __align__(16) float h1_s[BT * H1S];    // [b][h], h-contiguous
    __shared__ __align__(16) float w2f[Hsz * W2S];    // [k][h], h-contiguous
    __shared__ float W1_s[32], b1_s[32], b2_s[32], W3_s[32], sc[3];

    const int tid = threadIdx.x;
    const int o   = blockIdx.y;
    const int bt  = blockIdx.x;
    const int z   = blockIdx.z;

    const int tx = tid & 7;                // 8 k-groups:  k = tx + kk*8
    const int ty = tid >> 3;               // 16 row-groups: row = ty + r*16

    float oa[8];
    #pragma unroll
    for (int r = 0; r < 8; ++r) oa[r] = 0.f;

    const int i0 = z * IPB;
    for (int ii = 0; ii < IPB; ++ii) {
        const int i = i0 + ii;
        __syncthreads();                   // prev iteration's stage-C/epilogue readers done

        const int e = o * Isz + i;

        // ---- stage A1: issue W2 loads into registers (stay in flight) ----
        const float4* W2g4 = (const float4*)(W2 + (size_t)e * (Hsz * Hsz));
        const float4 wv0 = W2g4[tid];
        const float4 wv1 = W2g4[tid + THREADS];

        // ---- stage A2: small per-edge params -> smem ----
        if (tid < 32) {
            const int p = e * Hsz + tid;
            W1_s[tid] = W1[p]; b1_s[tid] = b1[p]; b2_s[tid] = b2[p]; W3_s[tid] = W3[p];
        } else if (tid == 32) sc[0] = b3[e];
        else if (tid == 33) sc[1] = lw[e];
        else if (tid == 34) sc[2] = bw[e];
        __syncthreads();                   // params visible (W2 LDGs still in flight)

        // ---- stage B: h1[b=tid][h], vectorized STS.128 ----
        const float xv = x[(size_t)(bt * BT + tid) * Isz + i];
        {
            float* dst = h1_s + tid * H1S;
            #pragma unroll
            for (int hc = 0; hc < 8; ++hc) {
                float4 v;
                v.x = leaky(fmaf(xv, W1_s[hc * 4 + 0], b1_s[hc * 4 + 0]));
                v.y = leaky(fmaf(xv, W1_s[hc * 4 + 1], b1_s[hc * 4 + 1]));
                v.z = leaky(fmaf(xv, W1_s[hc * 4 + 2], b1_s[hc * 4 + 2]));
                v.w = leaky(fmaf(xv, W1_s[hc * 4 + 3], b1_s[hc * 4 + 3]));
                *(float4*)(dst + hc * 4) = v;
            }
        }

        // ---- stage A3: land W2 registers into smem [k][h] ----
        {
            const int k0i = tid >> 3,         hc0 = tid & 7;            // idx = tid
            const int k1i = (tid + 128) >> 3, hc1 = tid & 7;            // idx = tid+128
            *(float4*)(w2f + k0i * W2S + hc0 * 4) = wv0;
            *(float4*)(w2f + k1i * W2S + hc1 * 4) = wv1;
        }
        __syncthreads();                   // h1 + w2f ready

        // ---- stage C: 8 rows x 4 k, f32x2 pairs along h ----
        unsigned long long acc[8][4];
        #pragma unroll
        for (int r = 0; r < 8; ++r)
            #pragma unroll
            for (int kk = 0; kk < 4; ++kk) acc[r][kk] = 0ull;

        #pragma unroll
        for (int hc = 0; hc < 8; ++hc) {              // 4 h per chunk
            ulonglong2 w[4];
            #pragma unroll
            for (int kk = 0; kk < 4; ++kk)
                w[kk] = *(const ulonglong2*)(w2f + (tx + kk * 8) * W2S + hc * 4);
            #pragma unroll
            for (int r = 0; r < 8; ++r) {
                const ulonglong2 a =
                    *(const ulonglong2*)(h1_s + (ty + r * 16) * H1S + hc * 4);
                FMA2(acc[r][0], a.x, w[0].x, acc[r][0]);
                FMA2(acc[r][1], a.x, w[1].x, acc[r][1]);
                FMA2(acc[r][2], a.x, w[2].x, acc[r][2]);
                FMA2(acc[r][3], a.x, w[3].x, acc[r][3]);
                FMA2(acc[r][0], a.y, w[0].y, acc[r][0]);
                FMA2(acc[r][1], a.y, w[1].y, acc[r][1]);
                FMA2(acc[r][2], a.y, w[2].y, acc[r][2]);
                FMA2(acc[r][3], a.y, w[3].y, acc[r][3]);
            }
        }

        // ---- epilogue: h2 = leaky(sum + b2), dot W3, reduce over 8 tx-lanes ----
        float pe[8];
        #pragma unroll
        for (int r = 0; r < 8; ++r) pe[r] = 0.f;
        #pragma unroll
        for (int kk = 0; kk < 4; ++kk) {
            const int k = tx + kk * 8;
            const float bb = b2_s[k], w3 = W3_s[k];
            #pragma unroll
            for (int r = 0; r < 8; ++r) {
                float lo, hi;
                asm("mov.b64 {%0,%1}, %2;" : "=f"(lo), "=f"(hi) : "l"(acc[r][kk]));
                pe[r] += leaky((lo + hi) + bb) * w3;
            }
        }
        #pragma unroll
        for (int m = 1; m < 8; m <<= 1)
            #pragma unroll
            for (int r = 0; r < 8; ++r)
                pe[r] += __shfl_xor_sync(0xffffffffu, pe[r], m);

        if (tx == 0) {
            const float vb3 = sc[0], vlw = sc[1], vbw = sc[2];
            #pragma unroll
            for (int r = 0; r < 8; ++r) {
                const float xq = x[(size_t)(bt * BT + ty + r * 16) * Isz + i];
                oa[r] += vlw * (pe[r] + vb3) + vbw * leaky(xq);
            }
        }
    }

    if (tx == 0) {
        float* dst = g_scratch + (size_t)z * (Bsz * Osz);
        #pragma unroll
        for (int r = 0; r < 8; ++r)
            dst[(size_t)(bt * BT + ty + r * 16) * Osz + o] = oa[r];
    }
}

__global__ void reduce_kernel(float* __restrict__ out)
{
    const int j = blockIdx.x * 256 + threadIdx.x;
    float s = 0.f;
    #pragma unroll
    for (int z = 0; z < ZSPLIT; ++z)
        s += g_scratch[(size_t)z * (Bsz * Osz) + j];
    out[j] = s;
}

extern "C" void kernel_launch(void* const* d_in, const int* in_sizes, int n_in,
                              void* d_out, int out_size)
{
    const float* x  = (const float*)d_in[0];
    const float* W1 = (const float*)d_in[1];
    const float* b1 = (const float*)d_in[2];
    const float* W2 = (const float*)d_in[3];
    const float* b2 = (const float*)d_in[4];
    const float* W3 = (const float*)d_in[5];
    const float* b3 = (const float*)d_in[6];
    const float* lw = (const float*)d_in[7];
    const float* bw = (const float*)d_in[8];
    float* out = (float*)d_out;

    dim3 grid(Bsz / BT, Osz, ZSPLIT);   // (8, 64, 4) = 2048 blocks
    kan_kernel<<<grid, THREADS>>>(x, W1, b1, W2, b2, W3, b3, lw, bw);
    reduce_kernel<<<(Bsz * Osz) / 256, 256>>>(out);
}

// round 15
// speedup vs baseline: 2.0955x; 2.0955x over previous
#include <cuda_runtime.h>
#include <cstdint>
#include <cfloat>

// KANLayer via per-edge piecewise-linear collapse.
// edge(x) = bw*leaky(x) + lw*( sum_k W3_k * leaky(P_k(seg) * x + Q_k(seg)) + b3 )
// where seg = #{h: t_h < x}, t_h = -b1_h/W1_h, and P,Q tables (33 segs x 32 k)
// are prebuilt per edge by rank-1 updates in sorted-threshold order.
// B=1024, I=64, O=64, H=32.

constexpr int Bsz = 1024, Isz = 64, Osz = 64, Hsz = 32;
constexpr int BLOB = 2176;            // per-edge: t[32] | W3[32] | PQ[33*32*2=2112]
constexpr int NEDGE = Osz * Isz;      // 4096

__device__ float g_tbl[NEDGE * BLOB]; // 35.7 MB
__device__ float g_xT[Isz * Bsz];     // x transposed [i][b]

__device__ __forceinline__ float leaky(float v) { return fmaxf(v, 0.01f * v); }

// ---------------- kernel 1: transpose x -> xT[i][b] ----------------
__global__ __launch_bounds__(128) void transpose_x(const float* __restrict__ x)
{
    __shared__ float tile[128 * 65];
    const int tid = threadIdx.x;
    const int b0  = blockIdx.x * 128;
    for (int j = tid; j < 128 * 64; j += 128) {
        const int b = j >> 6, i = j & 63;
        tile[b * 65 + i] = x[(size_t)(b0 + b) * Isz + i];
    }
    __syncthreads();
    for (int j = tid; j < 128 * 64; j += 128) {
        const int i = j >> 7, b = j & 127;
        g_xT[i * Bsz + b0 + b] = tile[b * 65 + i];
    }
}

// ---------------- kernel 2: build per-edge PWL tables ----------------
// one warp (32-thread block) per edge
__global__ __launch_bounds__(32) void build_tables(
    const float* __restrict__ W1, const float* __restrict__ b1,
    const float* __restrict__ W2, const float* __restrict__ b2,
    const float* __restrict__ W3)
{
    __shared__ float w2s[32 * 33];
    __shared__ float pq[2112];
    const int e    = blockIdx.x;
    const int lane = threadIdx.x;
    float* blob = g_tbl + (size_t)e * BLOB;

    // lane = h: threshold + base/delta coefficients
    const float w1  = W1[e * Hsz + lane];
    const float bb1 = b1[e * Hsz + lane];
    const float bb2 = b2[e * Hsz + lane];
    float t, s0, ds;
    if (w1 > 0.0f)      { t = -bb1 / w1; s0 = 0.01f; ds =  0.99f; }
    else if (w1 < 0.0f) { t = -bb1 / w1; s0 = 1.0f;  ds = -0.99f; }
    else                { t = FLT_MAX;   s0 = (bb1 >= 0.0f) ? 1.0f : 0.01f; ds = 0.0f; }

    blob[lane]      = t;                 // unsorted thresholds (count-based seg find)
    blob[32 + lane] = W3[e * Hsz + lane];

    const float a0 = s0 * w1, c0 = s0 * bb1;   // base coeffs (h-indexed, unsorted)
    float dp = ds * w1, dq = ds * bb1;         // crossing deltas (sorted below)
    float tk = t;
    int   hh = lane;

    // warp bitonic sort ascending by (tk, hh)
    #pragma unroll
    for (int k2 = 2; k2 <= 32; k2 <<= 1) {
        #pragma unroll
        for (int j = k2 >> 1; j > 0; j >>= 1) {
            const float ot = __shfl_xor_sync(~0u, tk, j);
            const float op = __shfl_xor_sync(~0u, dp, j);
            const float oq = __shfl_xor_sync(~0u, dq, j);
            const int   oh = __shfl_xor_sync(~0u, hh, j);
            const bool up      = ((lane & k2) == 0);
            const bool takemin = ((lane & j) == 0) ? up : !up;
            const bool iless   = (tk < ot) || (tk == ot && hh < oh);
            if (takemin != iless) { tk = ot; dp = op; dq = oq; hh = oh; }
        }
    }

    // stage W2[e][k][h] into smem, stride 33
    const float* W2g = W2 + (size_t)e * (Hsz * Hsz);
    #pragma unroll 8
    for (int r = 0; r < 32; ++r) w2s[r * 33 + lane] = W2g[r * 32 + lane];
    __syncwarp();

    // lane = k: base segment P,Q
    float p = 0.0f, q = bb2;
    #pragma unroll
    for (int h = 0; h < 32; ++h) {
        const float ah = __shfl_sync(~0u, a0, h);
        const float ch = __shfl_sync(~0u, c0, h);
        const float wv = w2s[lane * 33 + h];
        p = fmaf(ah, wv, p);
        q = fmaf(ch, wv, q);
    }
    pq[(lane * 33) * 2]     = p;
    pq[(lane * 33) * 2 + 1] = q;

    // 32 crossings in sorted order
    #pragma unroll
    for (int j = 0; j < 32; ++j) {
        const float pj = __shfl_sync(~0u, dp, j);
        const float qj = __shfl_sync(~0u, dq, j);
        const int   hj = __shfl_sync(~0u, hh, j);
        const float wv = w2s[lane * 33 + hj];
        p = fmaf(pj, wv, p);
        q = fmaf(qj, wv, q);
        pq[(lane * 33 + j + 1) * 2]     = p;
        pq[(lane * 33 + j + 1) * 2 + 1] = q;
    }
    __syncwarp();

    // coalesced write-out of PQ
    for (int j = lane; j < 2112; j += 32) blob[64 + j] = pq[j];
}

// ---------------- kernel 3: evaluate ----------------
// grid (8 b-tiles, 64 o), 128 threads; thread <-> one batch row
__global__ __launch_bounds__(128) void kan_eval(
    const float* __restrict__ b3, const float* __restrict__ lw,
    const float* __restrict__ bw, float* __restrict__ out)
{
    __shared__ __align__(16) float buf[2][BLOB];
    const int tid = threadIdx.x;
    const int bt  = blockIdx.x;
    const int o   = blockIdx.y;

    // prologue: load blob for i=0
    {
        const float* nb = g_tbl + (size_t)(o * Isz) * BLOB;
        #pragma unroll
        for (int r = 0; r < 17; ++r) buf[0][tid + r * 128] = nb[tid + r * 128];
    }
    __syncthreads();

    float oa = 0.0f;

    for (int i = 0; i < Isz; ++i) {
        const float* cur = buf[i & 1];
        float*       nxt = buf[(i + 1) & 1];
        const int    e   = o * Isz + i;

        // prefetch next blob into registers (overlaps eval)
        float pre[17];
        if (i < Isz - 1) {
            const float* nb = g_tbl + (size_t)(e + 1) * BLOB;
            #pragma unroll
            for (int r = 0; r < 17; ++r) pre[r] = __ldg(nb + tid + r * 128);
        }

        const float xv = g_xT[i * Bsz + bt * 128 + tid];

        // segment = count of thresholds below xv
        int seg = 0;
        #pragma unroll
        for (int h = 0; h < 32; ++h) seg += (xv > cur[h]) ? 1 : 0;

        // pe = sum_k W3_k * leaky(P_k*xv + Q_k)
        const float* PQ = cur + 64 + 2 * seg;
        float pe = 0.0f;
        #pragma unroll
        for (int k = 0; k < 32; ++k) {
            const float2 pqv = *(const float2*)(PQ + 66 * k);
            const float a2 = fmaf(pqv.x, xv, pqv.y);
            const float lk = fmaxf(a2, 0.01f * a2);
            pe = fmaf(lk, cur[32 + k], pe);
        }

        const float lwv = __ldg(lw + e), b3v = __ldg(b3 + e), bwv = __ldg(bw + e);
        oa += lwv * (pe + b3v) + bwv * leaky(xv);

        if (i < Isz - 1) {
            #pragma unroll
            for (int r = 0; r < 17; ++r) nxt[tid + r * 128] = pre[r];
        }
        __syncthreads();
    }

    out[(size_t)(bt * 128 + tid) * Osz + o] = oa;
}

extern "C" void kernel_launch(void* const* d_in, const int* in_sizes, int n_in,
                              void* d_out, int out_size)
{
    const float* x  = (const float*)d_in[0];
    const float* W1 = (const float*)d_in[1];
    const float* b1 = (const float*)d_in[2];
    const float* W2 = (const float*)d_in[3];
    const float* b2 = (const float*)d_in[4];
    const float* W3 = (const float*)d_in[5];
    const float* b3 = (const float*)d_in[6];
    const float* lw = (const float*)d_in[7];
    const float* bw = (const float*)d_in[8];
    float* out = (float*)d_out;

    transpose_x<<<Bsz / 128, 128>>>(x);
    build_tables<<<NEDGE, 32>>>(W1, b1, W2, b2, W3);
    dim3 grid(Bsz / 128, Osz);          // (8, 64)
    kan_eval<<<grid, 128>>>(b3, lw, bw, out);
}

// round 16
// speedup vs baseline: 2.5701x; 1.2265x over previous
#include <cuda_runtime.h>
#include <cstdint>
#include <math_constants.h>

// KANLayer via FULL piecewise-linear collapse.
// Per edge e, F_e(x) = lw*(sum_k W3_k*leaky(a2_k(x)) + b3) is exactly PWL:
// breakpoints = 32 first-layer kinks t_h  +  zeros of each a2_k (<=1 per k per
// segment). Build enumerates refined segments with (A,B) s.t. F_e = A*x + B.
// Eval: binary search + 1 FMA + bw*leaky(x).  B=1024, I=64, O=64, H=32.

constexpr int Bsz = 1024, Isz = 64, Osz = 64, Hsz = 32;
constexpr int NEDGE = Osz * Isz;       // 4096
constexpr int BPS = 1092;              // bp floats per edge (<=1088 bps + sentinel), 16B-mult
constexpr int ABS = 1090;              // (A,B) float2 per edge (<=1089 segments)

__device__ __align__(16) float  g_bp[(size_t)NEDGE * BPS];   // 17.9 MB
__device__ __align__(16) float2 g_ab[(size_t)NEDGE * ABS];   // 35.7 MB
__device__ int g_S[NEDGE];

__device__ __forceinline__ float leaky(float v) { return fmaxf(v, 0.01f * v); }

__device__ __forceinline__ float wsum(float v) {
    #pragma unroll
    for (int m = 16; m > 0; m >>= 1) v += __shfl_xor_sync(~0u, v, m);
    return v;
}
__device__ __forceinline__ float wmin(float v) {
    #pragma unroll
    for (int m = 16; m > 0; m >>= 1) v = fminf(v, __shfl_xor_sync(~0u, v, m));
    return v;
}

// ---------------- build: one warp per edge ----------------
__global__ __launch_bounds__(32) void build_pwl(
    const float* __restrict__ W1, const float* __restrict__ b1,
    const float* __restrict__ W2, const float* __restrict__ b2,
    const float* __restrict__ W3, const float* __restrict__ b3,
    const float* __restrict__ lw)
{
    __shared__ float w2s[32 * 33];
    const int e = blockIdx.x, lane = threadIdx.x;

    // lane = h: threshold + kink deltas; left-of-threshold coefficients
    const float w1 = W1[e * Hsz + lane], bb1 = b1[e * Hsz + lane];
    float t, dp, dq;
    if (w1 != 0.f) { t = -bb1 / w1; const float ds = (w1 > 0.f) ? 0.99f : -0.99f; dp = ds * w1; dq = ds * bb1; }
    else           { t = CUDART_INF_F; dp = 0.f; dq = 0.f; }
    const float sL = (w1 > 0.f) ? 0.01f : ((w1 < 0.f) ? 1.f : ((bb1 >= 0.f) ? 1.f : 0.01f));
    const float aL = sL * w1, cL = sL * bb1;

    // bitonic sort (t, dp, dq, h) ascending by (t, h)
    float tk = t, sp = dp, sq = dq; int hh = lane;
    #pragma unroll
    for (int k2 = 2; k2 <= 32; k2 <<= 1)
        #pragma unroll
        for (int j = k2 >> 1; j > 0; j >>= 1) {
            const float ot = __shfl_xor_sync(~0u, tk, j);
            const float op = __shfl_xor_sync(~0u, sp, j);
            const float oq = __shfl_xor_sync(~0u, sq, j);
            const int   oh = __shfl_xor_sync(~0u, hh, j);
            const bool up = ((lane & k2) == 0), tm = ((lane & j) == 0) ? up : !up;
            const bool less = (tk < ot) || (tk == ot && hh < oh);
            if (tm != less) { tk = ot; sp = op; sq = oq; hh = oh; }
        }

    // stage W2[e][k][h] (stride 33)
    const float* W2g = W2 + (size_t)e * (Hsz * Hsz);
    #pragma unroll 8
    for (int r = 0; r < 32; ++r) w2s[r * 33 + lane] = W2g[r * 32 + lane];
    __syncwarp();

    // lane = k: base-segment (x -> -inf) coefficients of a2_k = P*x + Q
    const float w3p = lw[e] * W3[e * Hsz + lane];
    float P = 0.f, Q = b2[e * Hsz + lane];
    #pragma unroll
    for (int h = 0; h < 32; ++h) {
        const float wv = w2s[lane * 33 + h];
        P = fmaf(__shfl_sync(~0u, aL, h), wv, P);
        Q = fmaf(__shfl_sync(~0u, cL, h), wv, Q);
    }
    const float lwb3 = lw[e] * b3[e];

    float*  obp = g_bp + (size_t)e * BPS;
    float2* oab = g_ab + (size_t)e * ABS;
    int nseg = 0;
    float lo = -CUDART_INF_F;

    for (int j = 0; j <= 32; ++j) {
        const float hi = (j < 32) ? __shfl_sync(~0u, tk, j) : CUDART_INF_F;

        // crossings of a2_k inside (lo, hi)
        const float x0 = -Q / P;                         // inf/nan if P==0: filtered below
        const bool valid = (P != 0.f) && (x0 > lo) && (x0 < hi);
        float xc = valid ? x0 : CUDART_INF_F;
        int remaining = __popc(__ballot_sync(~0u, valid));

        // s2 from midpoint of first sub-segment (fresh each first-layer segment)
        const float firstxc = wmin(xc);
        const float subhi = fminf(firstxc, hi);
        float xm;
        {
            const bool li = isinf(lo), hl = isinf(subhi);
            xm = (li && hl) ? 0.f : (li ? subhi - 1.f : (hl ? lo + 1.f : 0.5f * (lo + subhi)));
        }
        float s2 = (fmaf(P, xm, Q) > 0.f) ? 1.f : 0.01f;
        float A = wsum(w3p * s2 * P);
        float B = wsum(w3p * s2 * Q);

        if (lane == 0) {
            if (nseg > 0) obp[nseg - 1] = lo;
            oab[nseg] = make_float2(A, B + lwb3);
        }
        ++nseg;

        while (remaining > 0) {
            const float m = wmin(xc);
            const unsigned bal = __ballot_sync(~0u, xc == m);
            const int ks = __ffs(bal) - 1;
            const float Pk = __shfl_sync(~0u, P, ks), Qk = __shfl_sync(~0u, Q, ks);
            const float wk = __shfl_sync(~0u, w3p, ks), s2o = __shfl_sync(~0u, s2, ks);
            const float s2n = (s2o == 1.f) ? 0.01f : 1.f;
            if (lane == ks) { s2 = s2n; xc = CUDART_INF_F; }
            A += wk * (s2n - s2o) * Pk;
            B += wk * (s2n - s2o) * Qk;
            if (lane == 0) { obp[nseg - 1] = m; oab[nseg] = make_float2(A, B + lwb3); }
            ++nseg;
            --remaining;
        }

        if (j < 32) {   // apply first-layer kink j
            const float dpj = __shfl_sync(~0u, sp, j), dqj = __shfl_sync(~0u, sq, j);
            const int hj = __shfl_sync(~0u, hh, j);
            const float wc = w2s[lane * 33 + hj];
            P = fmaf(dpj, wc, P); Q = fmaf(dqj, wc, Q);
        }
        lo = hi;
    }
    if (lane == 0) { obp[nseg - 1] = CUDART_INF_F; g_S[e] = nseg - 1; }  // sentinel + count
}

// ---------------- eval ----------------
__device__ __forceinline__ uint32_t smem_u32(const void* p) {
    uint32_t a;
    asm("{ .reg .u64 t; cvta.to.shared.u64 t, %1; cvt.u32.u64 %0, t; }" : "=r"(a) : "l"(p));
    return a;
}
__device__ __forceinline__ void cpasync16(uint32_t s, const void* g) {
    asm volatile("cp.async.cg.shared.global [%0], [%1], 16;" :: "r"(s), "l"(g));
}

__global__ __launch_bounds__(128) void kan_eval(
    const float* __restrict__ x, const float* __restrict__ bw,
    float* __restrict__ out)
{
    __shared__ __align__(16) float  sbp[2][BPS];
    __shared__ __align__(16) float2 sab[2][ABS];
    const int tid = threadIdx.x, bt = blockIdx.x, o = blockIdx.y;
    const int e0 = o * Isz;
    const uint32_t bpA[2] = { smem_u32(sbp[0]), smem_u32(sbp[1]) };
    const uint32_t abA[2] = { smem_u32(sab[0]), smem_u32(sab[1]) };

    // stage i = 0 into buffer 0
    int Scur = __ldg(&g_S[e0]);
    {
        const int nb = (((Scur + 1) * 4) + 15) & ~15;
        const char* g = (const char*)(g_bp + (size_t)e0 * BPS);
        for (int ofs = tid * 16; ofs < nb; ofs += 2048) cpasync16(bpA[0] + ofs, g + ofs);
        const int na = (((Scur + 1) * 8) + 15) & ~15;
        const char* ga = (const char*)(g_ab + (size_t)e0 * ABS);
        for (int ofs = tid * 16; ofs < na; ofs += 2048) cpasync16(abA[0] + ofs, ga + ofs);
        asm volatile("cp.async.commit_group;");
        asm volatile("cp.async.wait_group 0;");
    }
    __syncthreads();

    const int brow = bt * 128 + tid;
    const float* xr = x + (size_t)brow * Isz;
    float oa = 0.f;

    for (int i = 0; i < Isz; ++i) {
        // prefetch table i+1 into the other buffer (overlaps eval)
        int Snext = 0;
        if (i + 1 < Isz) {
            const int en = e0 + i + 1;
            Snext = __ldg(&g_S[en]);
            const uint32_t db = bpA[(i + 1) & 1], da = abA[(i + 1) & 1];
            const int nb = (((Snext + 1) * 4) + 15) & ~15;
            const char* g = (const char*)(g_bp + (size_t)en * BPS);
            for (int ofs = tid * 16; ofs < nb; ofs += 2048) cpasync16(db + ofs, g + ofs);
            const int na = (((Snext + 1) * 8) + 15) & ~15;
            const char* ga = (const char*)(g_ab + (size_t)en * ABS);
            for (int ofs = tid * 16; ofs < na; ofs += 2048) cpasync16(da + ofs, ga + ofs);
        }
        asm volatile("cp.async.commit_group;");

        // evaluate current edge
        const float xv = xr[i];
        const float*  bp = sbp[i & 1];
        const float2* ab = sab[i & 1];
        int base = 0, n = Scur;
        #pragma unroll
        for (int it = 0; it < 11; ++it) {      // 2^11 >= max S; sentinel guards n==0 reads
            const int half = n >> 1;
            const float v = bp[base + half];
            const bool c = v < xv;
            base = c ? base + half + 1 : base;
            n = c ? n - half - 1 : half;
        }
        const float2 abv = ab[base];
        oa += fmaf(abv.x, xv, abv.y) + __ldg(&bw[e0 + i]) * leaky(xv);

        Scur = Snext;
        asm volatile("cp.async.wait_group 0;");
        __syncthreads();
    }

    out[(size_t)brow * Osz + o] = oa;
}

extern "C" void kernel_launch(void* const* d_in, const int* in_sizes, int n_in,
                              void* d_out, int out_size)
{
    const float* x  = (const float*)d_in[0];
    const float* W1 = (const float*)d_in[1];
    const float* b1 = (const float*)d_in[2];
    const float* W2 = (const float*)d_in[3];
    const float* b2 = (const float*)d_in[4];
    const float* W3 = (const float*)d_in[5];
    const float* b3 = (const float*)d_in[6];
    const float* lw = (const float*)d_in[7];
    const float* bw = (const float*)d_in[8];
    float* out = (float*)d_out;

    build_pwl<<<NEDGE, 32>>>(W1, b1, W2, b2, W3, b3, lw);
    dim3 grid(Bsz / 128, Osz);                 // (8, 64)
    kan_eval<<<grid, 128>>>(x, bw, out);
}